// round 8
// baseline (speedup 1.0000x reference)
#include <cuda_runtime.h>

#define N_SAMP 65536
#define K_CL   1024
#define D_DIM  512

// ---------------- device scratch (no allocs allowed) ----------------
__device__ float  g_e2[N_SAMP];
__device__ float  g_c2[K_CL];
__device__ int    g_s[N_SAMP];
__device__ int    g_k1[N_SAMP];   // best candidate (fp32)
__device__ int    g_k2[N_SAMP];   // runner-up candidate (fp32)
__device__ float  g_added[K_CL * D_DIM];
__device__ int    g_ncnt[K_CL];
__device__ double g_loss;

// ---------------- packed f32x2 helpers ----------------
__device__ __forceinline__ unsigned long long ffma2(unsigned long long a,
                                                    unsigned long long b,
                                                    unsigned long long c) {
    unsigned long long d;
    asm("fma.rn.f32x2 %0, %1, %2, %3;" : "=l"(d) : "l"(a), "l"(b), "l"(c));
    return d;
}
__device__ __forceinline__ unsigned long long pack2(float x) {
    unsigned long long d;
    asm("mov.b64 %0, {%1, %1};" : "=l"(d) : "f"(x));
    return d;
}
__device__ __forceinline__ void unpack2(unsigned long long v, float& lo, float& hi) {
    asm("mov.b64 {%0, %1}, %2;" : "=f"(lo), "=f"(hi) : "l"(v));
}

// top-2 insert with lowest-index tie-break
__device__ __forceinline__ void top2_ins(float d, int k, float& v1, int& i1,
                                         float& v2, int& i2) {
    if (d < v1 || (d == v1 && k < i1)) { v2 = v1; i2 = i1; v1 = d; i1 = k; }
    else if (d < v2 || (d == v2 && k < i2)) { v2 = d; i2 = k; }
}

// ---------------- zero scratch ----------------
__global__ void k_zero() {
    int i = blockIdx.x * blockDim.x + threadIdx.x;
    if (i < K_CL * D_DIM) g_added[i] = 0.0f;
    if (i < K_CL) g_ncnt[i] = 0;
    if (i == 0) g_loss = 0.0;
}

// ---------------- row squared norms (which=0 -> g_e2, which=1 -> g_c2) ----------------
__global__ void k_rownorm(const float* __restrict__ x, int rows, int which) {
    int warp = (blockIdx.x * blockDim.x + threadIdx.x) >> 5;
    int lane = threadIdx.x & 31;
    if (warp >= rows) return;
    const float4* r = (const float4*)(x + (size_t)warp * D_DIM);
    float s = 0.0f;
#pragma unroll
    for (int i = lane; i < D_DIM / 4; i += 32) {
        float4 v = r[i];
        s += v.x * v.x + v.y * v.y + v.z * v.z + v.w * v.w;
    }
#pragma unroll
    for (int o = 16; o; o >>= 1) s += __shfl_xor_sync(0xFFFFFFFFu, s, o);
    if (lane == 0) {
        if (which) g_c2[warp] = s; else g_e2[warp] = s;
    }
}

// ---------------- main: fused GEMM + top-2 argmin ----------------
#define MT 128
#define NT 64
#define KT 16
#define AS_STRIDE (MT + 4)
#define BS_STRIDE (NT + 4)

__global__ __launch_bounds__(256, 2) void k_main(const float* __restrict__ E,
                                                 const float* __restrict__ C) {
    __shared__ __align__(16) float As[KT][AS_STRIDE];
    __shared__ __align__(16) float Bs[KT][BS_STRIDE];
    __shared__ float lsum[16];

    const int tid = threadIdx.x;
    const int tx = tid & 15;   // column group (4 centers each)
    const int ty = tid >> 4;   // row group (8 rows each)
    const int m0 = blockIdx.x * MT;

    float v1[8], v2[8];
    int   i1[8], i2[8];
#pragma unroll
    for (int r = 0; r < 8; r++) { v1[r] = 3.4e38f; v2[r] = 3.4e38f; i1[r] = 0; i2[r] = 0; }

    for (int kt = 0; kt < K_CL / NT; kt++) {
        const int k0 = kt * NT;
        unsigned long long acc2[4][4];
#pragma unroll
        for (int p = 0; p < 4; p++)
#pragma unroll
            for (int j = 0; j < 4; j++) acc2[p][j] = 0ull;

        for (int dc = 0; dc < D_DIM / KT; dc++) {
            const int d0 = dc * KT;
            __syncthreads();
#pragma unroll
            for (int l = tid; l < MT * KT / 4; l += 256) {
                int m = l >> 2, c4 = l & 3;
                float4 v = ((const float4*)(E + (size_t)(m0 + m) * D_DIM + d0))[c4];
                As[c4 * 4 + 0][m] = v.x;
                As[c4 * 4 + 1][m] = v.y;
                As[c4 * 4 + 2][m] = v.z;
                As[c4 * 4 + 3][m] = v.w;
            }
            {
                int l = tid;
                int kr = l >> 2, c4 = l & 3;
                float4 v = ((const float4*)(C + (size_t)(k0 + kr) * D_DIM + d0))[c4];
                Bs[c4 * 4 + 0][kr] = v.x;
                Bs[c4 * 4 + 1][kr] = v.y;
                Bs[c4 * 4 + 2][kr] = v.z;
                Bs[c4 * 4 + 3][kr] = v.w;
            }
            __syncthreads();

#pragma unroll
            for (int dd = 0; dd < KT; dd++) {
                ulonglong2 a01 = *(const ulonglong2*)&As[dd][ty * 8];
                ulonglong2 a23 = *(const ulonglong2*)&As[dd][ty * 8 + 4];
                float4 bf = *(const float4*)&Bs[dd][tx * 4];
                unsigned long long b0 = pack2(bf.x);
                unsigned long long b1 = pack2(bf.y);
                unsigned long long b2 = pack2(bf.z);
                unsigned long long b3 = pack2(bf.w);
                acc2[0][0] = ffma2(a01.x, b0, acc2[0][0]);
                acc2[0][1] = ffma2(a01.x, b1, acc2[0][1]);
                acc2[0][2] = ffma2(a01.x, b2, acc2[0][2]);
                acc2[0][3] = ffma2(a01.x, b3, acc2[0][3]);
                acc2[1][0] = ffma2(a01.y, b0, acc2[1][0]);
                acc2[1][1] = ffma2(a01.y, b1, acc2[1][1]);
                acc2[1][2] = ffma2(a01.y, b2, acc2[1][2]);
                acc2[1][3] = ffma2(a01.y, b3, acc2[1][3]);
                acc2[2][0] = ffma2(a23.x, b0, acc2[2][0]);
                acc2[2][1] = ffma2(a23.x, b1, acc2[2][1]);
                acc2[2][2] = ffma2(a23.x, b2, acc2[2][2]);
                acc2[2][3] = ffma2(a23.x, b3, acc2[2][3]);
                acc2[3][0] = ffma2(a23.y, b0, acc2[3][0]);
                acc2[3][1] = ffma2(a23.y, b1, acc2[3][1]);
                acc2[3][2] = ffma2(a23.y, b2, acc2[3][2]);
                acc2[3][3] = ffma2(a23.y, b3, acc2[3][3]);
            }
        }

        // epilogue: dist = c2[k] - 2*cross (e2 added later), track top-2
        const int kbase = k0 + tx * 4;
        float c2v[4];
#pragma unroll
        for (int j = 0; j < 4; j++) c2v[j] = g_c2[kbase + j];
#pragma unroll
        for (int p = 0; p < 4; p++) {
#pragma unroll
            for (int j = 0; j < 4; j++) {
                float lo, hi;
                unpack2(acc2[p][j], lo, hi);
                float dlo = c2v[j] - 2.0f * lo;
                float dhi = c2v[j] - 2.0f * hi;
                top2_ins(dlo, kbase + j, v1[2 * p],     i1[2 * p],     v2[2 * p],     i2[2 * p]);
                top2_ins(dhi, kbase + j, v1[2 * p + 1], i1[2 * p + 1], v2[2 * p + 1], i2[2 * p + 1]);
            }
        }
    }

    // reduce top-2 across the 16 column-threads sharing each row
    float lpart = 0.0f;
#pragma unroll
    for (int r = 0; r < 8; r++) {
        float a1 = v1[r], a2 = v2[r];
        int   b1 = i1[r], b2 = i2[r];
#pragma unroll
        for (int o = 8; o; o >>= 1) {
            float ov1 = __shfl_xor_sync(0xFFFFFFFFu, a1, o);
            int   oi1 = __shfl_xor_sync(0xFFFFFFFFu, b1, o);
            float ov2 = __shfl_xor_sync(0xFFFFFFFFu, a2, o);
            int   oi2 = __shfl_xor_sync(0xFFFFFFFFu, b2, o);
            top2_ins(ov1, oi1, a1, b1, a2, b2);
            top2_ins(ov2, oi2, a1, b1, a2, b2);
        }
        if (tx == 0) {
            int m = m0 + ty * 8 + r;
            g_k1[m] = b1;
            g_k2[m] = b2;
            lpart += a1 + g_e2[m];
        }
    }
    if (tx == 0) lsum[ty] = lpart;
    __syncthreads();
    if (tid == 0) {
        double t = 0.0;
#pragma unroll
        for (int i = 0; i < 16; i++) t += (double)lsum[i];
        atomicAdd(&g_loss, t);
    }
}

// ---------------- fp64 refinement of the top-2 candidates ----------------
// One warp per sample: exact ||e-c||^2 for both candidates, pick true argmin.
__global__ __launch_bounds__(256) void k_refine(const float* __restrict__ E,
                                                const float* __restrict__ C,
                                                float* __restrict__ out_s) {
    int warp = (blockIdx.x * blockDim.x + threadIdx.x) >> 5;
    int lane = threadIdx.x & 31;
    if (warp >= N_SAMP) return;
    int k1 = g_k1[warp];
    int k2 = g_k2[warp];
    const float4* e4 = (const float4*)(E + (size_t)warp * D_DIM);
    const float4* a4 = (const float4*)(C + (size_t)k1 * D_DIM);
    const float4* b4 = (const float4*)(C + (size_t)k2 * D_DIM);
    double s1 = 0.0, s2 = 0.0;
#pragma unroll
    for (int i = lane; i < D_DIM / 4; i += 32) {
        float4 e = e4[i];
        float4 a = a4[i];
        float4 b = b4[i];
        double dx, dy, dz, dw;
        dx = (double)e.x - (double)a.x; dy = (double)e.y - (double)a.y;
        dz = (double)e.z - (double)a.z; dw = (double)e.w - (double)a.w;
        s1 += dx * dx + dy * dy + dz * dz + dw * dw;
        dx = (double)e.x - (double)b.x; dy = (double)e.y - (double)b.y;
        dz = (double)e.z - (double)b.z; dw = (double)e.w - (double)b.w;
        s2 += dx * dx + dy * dy + dz * dz + dw * dw;
    }
#pragma unroll
    for (int o = 16; o; o >>= 1) {
        s1 += __shfl_xor_sync(0xFFFFFFFFu, s1, o);
        s2 += __shfl_xor_sync(0xFFFFFFFFu, s2, o);
    }
    if (lane == 0) {
        int k;
        if (s1 < s2)      k = k1;
        else if (s2 < s1) k = k2;
        else              k = (k1 < k2) ? k1 : k2;
        g_s[warp] = k;
        out_s[warp] = (float)k;
    }
}

// ---------------- segment sums via spread atomics ----------------
__global__ void k_seg(const float* __restrict__ E) {
    int t = blockIdx.x * blockDim.x + threadIdx.x;  // N * 128 threads
    int n = t >> 7;
    int q = t & 127;
    if (n >= N_SAMP) return;
    int s = g_s[n];
    float4 v = ((const float4*)(E + (size_t)n * D_DIM))[q];
    float* dst = &g_added[(size_t)s * D_DIM + q * 4];
    atomicAdd(dst + 0, v.x);
    atomicAdd(dst + 1, v.y);
    atomicAdd(dst + 2, v.z);
    atomicAdd(dst + 3, v.w);
    if (q == 0) atomicAdd(&g_ncnt[s], 1);
}

// ---------------- finalize: new centers, new counts, loss ----------------
// NOTE: out + 1 + N_SAMP is an ODD float offset -> scalar stores only.
__global__ void k_fin(const float* __restrict__ C, const int* __restrict__ cnt_in,
                      float* __restrict__ out) {
    int k = blockIdx.x;
    int d4 = threadIdx.x;  // 128 threads
    int c0 = cnt_in[k];
    int nc = c0 + g_ncnt[k];
    float cf = (float)c0;
    float inv = 1.0f / (float)nc;
    float4 cv = ((const float4*)(C + (size_t)k * D_DIM))[d4];
    const float* ad = &g_added[(size_t)k * D_DIM + d4 * 4];
    float* dst = out + 1 + N_SAMP + (size_t)k * D_DIM + d4 * 4;
    dst[0] = (cf * cv.x + ad[0]) * inv;
    dst[1] = (cf * cv.y + ad[1]) * inv;
    dst[2] = (cf * cv.z + ad[2]) * inv;
    dst[3] = (cf * cv.w + ad[3]) * inv;
    if (d4 == 0) {
        out[1 + N_SAMP + (size_t)K_CL * D_DIM + k] = (float)nc;
        if (k == 0) out[0] = (float)(g_loss / (double)N_SAMP);
    }
}

extern "C" void kernel_launch(void* const* d_in, const int* in_sizes, int n_in,
                              void* d_out, int out_size) {
    (void)in_sizes; (void)n_in; (void)out_size;
    const float* E   = (const float*)d_in[0];
    const float* C   = (const float*)d_in[1];
    const int*   cnt = (const int*)d_in[2];
    float* out = (float*)d_out;

    k_zero<<<(K_CL * D_DIM + 255) / 256, 256>>>();
    k_rownorm<<<(N_SAMP * 32 + 255) / 256, 256>>>(E, N_SAMP, 0);
    k_rownorm<<<(K_CL * 32 + 255) / 256, 256>>>(C, K_CL, 1);
    k_main<<<N_SAMP / MT, 256>>>(E, C);
    k_refine<<<(N_SAMP * 32 + 255) / 256, 256>>>(E, C, out + 1);
    k_seg<<<(N_SAMP * 128 + 255) / 256, 256>>>(E);
    k_fin<<<K_CL, 128>>>(C, cnt, out);
}

// round 10
// speedup vs baseline: 1.5547x; 1.5547x over previous
#include <cuda_runtime.h>
#include <cuda_bf16.h>
#include <cstdint>

#define N_SAMP 65536
#define K_CL   1024
#define D_DIM  512

// ---------------- device scratch (no allocs allowed) ----------------
__device__ float  g_c2[K_CL];
__device__ int    g_s[N_SAMP];
__device__ int    g_k1[N_SAMP];
__device__ int    g_k2[N_SAMP];
__device__ float  g_added[K_CL * D_DIM];
__device__ int    g_ncnt[K_CL];
__device__ double g_loss;
// split-bf16: [row][0..511]=hi, [row][512..1023]=lo
__device__ unsigned short g_Ebf[(size_t)N_SAMP * 1024];
__device__ unsigned short g_Cbf[(size_t)K_CL * 1024];

// ---------------- baseline-PTX helpers (sm_80-class: compiles on sm_103) ----
__device__ __forceinline__ uint32_t smem_u32(const void* p) {
    uint32_t a;
    asm("{ .reg .u64 t; cvta.to.shared.u64 t, %1; cvt.u32.u64 %0, t; }" : "=r"(a) : "l"(p));
    return a;
}
__device__ __forceinline__ void cp_async16(uint32_t dst, const void* src) {
    asm volatile("cp.async.cg.shared.global [%0], [%1], 16;" :: "r"(dst), "l"(src));
}
__device__ __forceinline__ void cp_commit() {
    asm volatile("cp.async.commit_group;" ::: "memory");
}
template <int N> __device__ __forceinline__ void cp_wait() {
    asm volatile("cp.async.wait_group %0;" :: "n"(N) : "memory");
}
__device__ __forceinline__ void ldm4(uint32_t* r, uint32_t addr) {
    asm volatile("ldmatrix.sync.aligned.m8n8.x4.shared.b16 {%0,%1,%2,%3}, [%4];"
                 : "=r"(r[0]), "=r"(r[1]), "=r"(r[2]), "=r"(r[3]) : "r"(addr));
}
__device__ __forceinline__ void mma16816(float* d, const uint32_t* a, uint32_t b0,
                                         uint32_t b1) {
    asm volatile(
        "mma.sync.aligned.m16n8k16.row.col.f32.bf16.bf16.f32 "
        "{%0,%1,%2,%3}, {%4,%5,%6,%7}, {%8,%9}, {%0,%1,%2,%3};"
        : "+f"(d[0]), "+f"(d[1]), "+f"(d[2]), "+f"(d[3])
        : "r"(a[0]), "r"(a[1]), "r"(a[2]), "r"(a[3]), "r"(b0), "r"(b1));
}
static __device__ __forceinline__ uint32_t swz(uint32_t o) {
    return o ^ ((o >> 3) & 0x70);   // SW128: 16B-granular XOR within 128B rows
}

// top-2 insert with lowest-index tie-break
__device__ __forceinline__ void top2_ins(float d, int k, float& v1, int& i1,
                                         float& v2, int& i2) {
    if (d < v1 || (d == v1 && k < i1)) { v2 = v1; i2 = i1; v1 = d; i1 = k; }
    else if (d < v2 || (d == v2 && k < i2)) { v2 = d; i2 = k; }
}

// ---------------- zero scratch ----------------
__global__ void k_zero() {
    int i = blockIdx.x * blockDim.x + threadIdx.x;
    if (i < K_CL * D_DIM) g_added[i] = 0.0f;
    if (i < K_CL) g_ncnt[i] = 0;
    if (i == 0) g_loss = 0.0;
}

// ---------------- fp32 -> split bf16 (hi, lo) ----------------
__global__ void k_conv(const float* __restrict__ src, unsigned short* __restrict__ dst,
                       int rows) {
    int idx = blockIdx.x * blockDim.x + threadIdx.x;  // one float4 each
    int total = rows * (D_DIM / 4);
    if (idx >= total) return;
    int row = idx >> 7;
    int c4 = (idx & 127) * 4;
    float4 v = ((const float4*)src)[idx];
    ushort4 hi, lo;
    __nv_bfloat16 h;
    h = __float2bfloat16(v.x); hi.x = __bfloat16_as_ushort(h);
    lo.x = __bfloat16_as_ushort(__float2bfloat16(v.x - __bfloat162float(h)));
    h = __float2bfloat16(v.y); hi.y = __bfloat16_as_ushort(h);
    lo.y = __bfloat16_as_ushort(__float2bfloat16(v.y - __bfloat162float(h)));
    h = __float2bfloat16(v.z); hi.z = __bfloat16_as_ushort(h);
    lo.z = __bfloat16_as_ushort(__float2bfloat16(v.z - __bfloat162float(h)));
    h = __float2bfloat16(v.w); hi.w = __bfloat16_as_ushort(h);
    lo.w = __bfloat16_as_ushort(__float2bfloat16(v.w - __bfloat162float(h)));
    *(ushort4*)(dst + (size_t)row * 1024 + c4) = hi;
    *(ushort4*)(dst + (size_t)row * 1024 + 512 + c4) = lo;
}

// ---------------- center squared norms ----------------
__global__ void k_rownorm_c(const float* __restrict__ x) {
    int warp = (blockIdx.x * blockDim.x + threadIdx.x) >> 5;
    int lane = threadIdx.x & 31;
    if (warp >= K_CL) return;
    const float4* r = (const float4*)(x + (size_t)warp * D_DIM);
    float s = 0.0f;
#pragma unroll
    for (int i = lane; i < D_DIM / 4; i += 32) {
        float4 v = r[i];
        s += v.x * v.x + v.y * v.y + v.z * v.z + v.w * v.w;
    }
#pragma unroll
    for (int o = 16; o; o >>= 1) s += __shfl_xor_sync(0xFFFFFFFFu, s, o);
    if (lane == 0) g_c2[warp] = s;
}

// ---------------- main: mma.sync bf16 split GEMM + top-2 argmin ----------------
// SMEM (dynamic): A bufs 2x16KB, B bufs 2x16KB, c2 4KB, reduction 8KB
#define SA0 0
#define SA1 16384
#define SB0 32768
#define SB1 49152
#define SC2 65536
#define SRED 69632
#define SMEM_TT (SRED + 128 * 4 * 16)   // 77824

__global__ __launch_bounds__(256) void k_main_mma() {
    extern __shared__ __align__(1024) char smem[];
    const uint32_t sb = smem_u32(smem);
    const int tid = threadIdx.x;
    const int lane = tid & 31;
    const int wid = tid >> 5;
    const int warp_m = wid & 1;    // 2 row groups of 64
    const int warp_n = wid >> 1;   // 4 col groups of 32
    const int m0 = blockIdx.x * 128;
    float* c2s = (float*)(smem + SC2);

    for (int i = tid; i < K_CL; i += 256) c2s[i] = g_c2[i];
    __syncthreads();

    float acc[4][4][4];
    float tv1[8], tv2[8];
    int   ti1[8], ti2[8];
#pragma unroll
    for (int s = 0; s < 8; s++) { tv1[s] = 3.4e38f; tv2[s] = 3.4e38f; ti1[s] = 0; ti2[s] = 0; }
#pragma unroll
    for (int a = 0; a < 4; a++)
#pragma unroll
        for (int b = 0; b < 4; b++)
#pragma unroll
            for (int c = 0; c < 4; c++) acc[a][b][c] = 0.0f;

    for (int ch = 0; ch < 8; ch++) {
        const int nc0 = ch * 128;
        // ---- stage slab 0 ----
        {
            const int ak = 0, bk = 0;
            uint32_t abuf = sb + SA0, bbuf = sb + SB0;
#pragma unroll
            for (int i = 0; i < 4; i++) {
                int l = tid + i * 256;
                int m = l >> 3, c = l & 7;
                cp_async16(abuf + swz(m * 128 + c * 16),
                           g_Ebf + (size_t)(m0 + m) * 1024 + ak + c * 8);
            }
#pragma unroll
            for (int i = 0; i < 4; i++) {
                int l = tid + i * 256;
                int n = l >> 3, c = l & 7;
                cp_async16(bbuf + swz(n * 128 + c * 16),
                           g_Cbf + (size_t)(nc0 + n) * 1024 + bk + c * 8);
            }
            cp_commit();
        }
        for (int it = 0; it < 24; it++) {
            if (it < 23) {
                const int slab = it + 1;
                const int pass = slab >> 3, j = slab & 7;
                const int ak = ((pass == 2) ? 512 : 0) + j * 64;
                const int bk = ((pass == 1) ? 512 : 0) + j * 64;
                const int nb = slab & 1;
                uint32_t abuf = sb + (nb ? SA1 : SA0);
                uint32_t bbuf = sb + (nb ? SB1 : SB0);
#pragma unroll
                for (int i = 0; i < 4; i++) {
                    int l = tid + i * 256;
                    int m = l >> 3, c = l & 7;
                    cp_async16(abuf + swz(m * 128 + c * 16),
                               g_Ebf + (size_t)(m0 + m) * 1024 + ak + c * 8);
                }
#pragma unroll
                for (int i = 0; i < 4; i++) {
                    int l = tid + i * 256;
                    int n = l >> 3, c = l & 7;
                    cp_async16(bbuf + swz(n * 128 + c * 16),
                               g_Cbf + (size_t)(nc0 + n) * 1024 + bk + c * 8);
                }
                cp_commit();
                cp_wait<1>();
            } else {
                cp_wait<0>();
            }
            __syncthreads();
            // ---- compute on buf it&1 ----
            {
                uint32_t ab = sb + ((it & 1) ? SA1 : SA0);
                uint32_t bb = sb + ((it & 1) ? SB1 : SB0);
#pragma unroll
                for (int ks = 0; ks < 4; ks++) {
                    uint32_t ar[4][4], br[2][4];
#pragma unroll
                    for (int mf = 0; mf < 4; mf++) {
                        uint32_t addr = ab + swz((warp_m * 64 + mf * 16 + (lane & 15)) * 128 +
                                                 ks * 32 + (lane >> 4) * 16);
                        ldm4(ar[mf], addr);
                    }
#pragma unroll
                    for (int bt = 0; bt < 2; bt++) {
                        int n = warp_n * 32 + bt * 16 + (lane & 7) + ((lane >> 4) & 1) * 8;
                        uint32_t addr = bb + swz(n * 128 + ks * 32 + ((lane >> 3) & 1) * 16);
                        ldm4(br[bt], addr);
                    }
#pragma unroll
                    for (int mf = 0; mf < 4; mf++)
#pragma unroll
                        for (int nf = 0; nf < 4; nf++)
                            mma16816(acc[mf][nf], ar[mf],
                                     br[nf >> 1][(nf & 1) * 2], br[nf >> 1][(nf & 1) * 2 + 1]);
                }
            }
            __syncthreads();
        }
        // ---- epilogue for this 128-center chunk: dist = c2 - 2*cross, top-2 ----
#pragma unroll
        for (int mf = 0; mf < 4; mf++)
#pragma unroll
            for (int nf = 0; nf < 4; nf++) {
                int kb = nc0 + warp_n * 32 + nf * 8 + 2 * (lane & 3);
                float d0 = c2s[kb] - 2.0f * acc[mf][nf][0];
                float d1 = c2s[kb + 1] - 2.0f * acc[mf][nf][1];
                float d2 = c2s[kb] - 2.0f * acc[mf][nf][2];
                float d3 = c2s[kb + 1] - 2.0f * acc[mf][nf][3];
                int s0 = mf * 2, s1 = mf * 2 + 1;
                top2_ins(d0, kb,     tv1[s0], ti1[s0], tv2[s0], ti2[s0]);
                top2_ins(d1, kb + 1, tv1[s0], ti1[s0], tv2[s0], ti2[s0]);
                top2_ins(d2, kb,     tv1[s1], ti1[s1], tv2[s1], ti2[s1]);
                top2_ins(d3, kb + 1, tv1[s1], ti1[s1], tv2[s1], ti2[s1]);
                acc[mf][nf][0] = 0.0f; acc[mf][nf][1] = 0.0f;
                acc[mf][nf][2] = 0.0f; acc[mf][nf][3] = 0.0f;
            }
    }

    // ---- intra-warp top-2 reduce across the 4 lanes sharing each row ----
#pragma unroll
    for (int s = 0; s < 8; s++) {
#pragma unroll
        for (int o = 1; o <= 2; o <<= 1) {
            float ov1 = __shfl_xor_sync(0xFFFFFFFFu, tv1[s], o);
            int   oi1 = __shfl_xor_sync(0xFFFFFFFFu, ti1[s], o);
            float ov2 = __shfl_xor_sync(0xFFFFFFFFu, tv2[s], o);
            int   oi2 = __shfl_xor_sync(0xFFFFFFFFu, ti2[s], o);
            top2_ins(ov1, oi1, tv1[s], ti1[s], tv2[s], ti2[s]);
            top2_ins(ov2, oi2, tv1[s], ti1[s], tv2[s], ti2[s]);
        }
    }
    // ---- cross-warp_n merge via SMEM ----
    int4* red = (int4*)(smem + SRED);
    if ((lane & 3) == 0) {
#pragma unroll
        for (int s = 0; s < 8; s++) {
            int r = warp_m * 64 + (s >> 1) * 16 + (s & 1) * 8 + (lane >> 2);
            int4 v;
            v.x = __float_as_int(tv1[s]); v.y = ti1[s];
            v.z = __float_as_int(tv2[s]); v.w = ti2[s];
            red[r * 4 + warp_n] = v;
        }
    }
    __syncthreads();
    if (tid < 128) {
        float v1 = 3.4e38f, v2 = 3.4e38f;
        int i1 = 0, i2 = 0;
#pragma unroll
        for (int w = 0; w < 4; w++) {
            int4 v = red[tid * 4 + w];
            top2_ins(__int_as_float(v.x), v.y, v1, i1, v2, i2);
            top2_ins(__int_as_float(v.z), v.w, v1, i1, v2, i2);
        }
        g_k1[m0 + tid] = i1;
        g_k2[m0 + tid] = i2;
    }
}

// ---------------- fp64 refinement + exact loss ----------------
__global__ __launch_bounds__(256) void k_refine(const float* __restrict__ E,
                                                const float* __restrict__ C,
                                                float* __restrict__ out_s) {
    __shared__ double ls[8];
    int warp = (blockIdx.x * blockDim.x + threadIdx.x) >> 5;
    int lane = threadIdx.x & 31;
    int wib = threadIdx.x >> 5;
    double mn = 0.0;
    if (warp < N_SAMP) {
        int k1 = g_k1[warp];
        int k2 = g_k2[warp];
        const float4* e4 = (const float4*)(E + (size_t)warp * D_DIM);
        const float4* a4 = (const float4*)(C + (size_t)k1 * D_DIM);
        const float4* b4 = (const float4*)(C + (size_t)k2 * D_DIM);
        double s1 = 0.0, s2 = 0.0;
#pragma unroll
        for (int i = lane; i < D_DIM / 4; i += 32) {
            float4 e = e4[i];
            float4 a = a4[i];
            float4 b = b4[i];
            double dx, dy, dz, dw;
            dx = (double)e.x - (double)a.x; dy = (double)e.y - (double)a.y;
            dz = (double)e.z - (double)a.z; dw = (double)e.w - (double)a.w;
            s1 += dx * dx + dy * dy + dz * dz + dw * dw;
            dx = (double)e.x - (double)b.x; dy = (double)e.y - (double)b.y;
            dz = (double)e.z - (double)b.z; dw = (double)e.w - (double)b.w;
            s2 += dx * dx + dy * dy + dz * dz + dw * dw;
        }
#pragma unroll
        for (int o = 16; o; o >>= 1) {
            s1 += __shfl_xor_sync(0xFFFFFFFFu, s1, o);
            s2 += __shfl_xor_sync(0xFFFFFFFFu, s2, o);
        }
        if (lane == 0) {
            int k;
            if (s1 < s2)      { k = k1; mn = s1; }
            else if (s2 < s1) { k = k2; mn = s2; }
            else              { k = (k1 < k2) ? k1 : k2; mn = s1; }
            g_s[warp] = k;
            out_s[warp] = (float)k;
        }
    }
    if (lane == 0) ls[wib] = mn;
    __syncthreads();
    if (threadIdx.x == 0) {
        double t = 0.0;
#pragma unroll
        for (int i = 0; i < 8; i++) t += ls[i];
        atomicAdd(&g_loss, t);
    }
}

// ---------------- segment sums via spread atomics ----------------
__global__ void k_seg(const float* __restrict__ E) {
    int t = blockIdx.x * blockDim.x + threadIdx.x;
    int n = t >> 7;
    int q = t & 127;
    if (n >= N_SAMP) return;
    int s = g_s[n];
    float4 v = ((const float4*)(E + (size_t)n * D_DIM))[q];
    float* dst = &g_added[(size_t)s * D_DIM + q * 4];
    atomicAdd(dst + 0, v.x);
    atomicAdd(dst + 1, v.y);
    atomicAdd(dst + 2, v.z);
    atomicAdd(dst + 3, v.w);
    if (q == 0) atomicAdd(&g_ncnt[s], 1);
}

// ---------------- finalize (scalar stores: out+1+N is odd offset) ----------------
__global__ void k_fin(const float* __restrict__ C, const int* __restrict__ cnt_in,
                      float* __restrict__ out) {
    int k = blockIdx.x;
    int d4 = threadIdx.x;
    int c0 = cnt_in[k];
    int nc = c0 + g_ncnt[k];
    float cf = (float)c0;
    float inv = 1.0f / (float)nc;
    float4 cv = ((const float4*)(C + (size_t)k * D_DIM))[d4];
    const float* ad = &g_added[(size_t)k * D_DIM + d4 * 4];
    float* dst = out + 1 + N_SAMP + (size_t)k * D_DIM + d4 * 4;
    dst[0] = (cf * cv.x + ad[0]) * inv;
    dst[1] = (cf * cv.y + ad[1]) * inv;
    dst[2] = (cf * cv.z + ad[2]) * inv;
    dst[3] = (cf * cv.w + ad[3]) * inv;
    if (d4 == 0) {
        out[1 + N_SAMP + (size_t)K_CL * D_DIM + k] = (float)nc;
        if (k == 0) out[0] = (float)(g_loss / (double)N_SAMP);
    }
}

extern "C" void kernel_launch(void* const* d_in, const int* in_sizes, int n_in,
                              void* d_out, int out_size) {
    (void)in_sizes; (void)n_in; (void)out_size;
    const float* E   = (const float*)d_in[0];
    const float* C   = (const float*)d_in[1];
    const int*   cnt = (const int*)d_in[2];
    float* out = (float*)d_out;

    unsigned short* ebf_p = nullptr;
    unsigned short* cbf_p = nullptr;
    cudaGetSymbolAddress((void**)&ebf_p, g_Ebf);
    cudaGetSymbolAddress((void**)&cbf_p, g_Cbf);
    cudaFuncSetAttribute(k_main_mma, cudaFuncAttributeMaxDynamicSharedMemorySize,
                         SMEM_TT);

    k_zero<<<(K_CL * D_DIM + 255) / 256, 256>>>();
    k_conv<<<(N_SAMP * 128 + 255) / 256, 256>>>(E, ebf_p, N_SAMP);
    k_conv<<<(K_CL * 128 + 255) / 256, 256>>>(C, cbf_p, K_CL);
    k_rownorm_c<<<(K_CL * 32 + 255) / 256, 256>>>(C);
    k_main_mma<<<N_SAMP / 128, 256, SMEM_TT>>>();
    k_refine<<<(N_SAMP * 32 + 255) / 256, 256>>>(E, C, out + 1);
    k_seg<<<(N_SAMP * 128 + 255) / 256, 256>>>(E);
    k_fin<<<K_CL, 128>>>(C, cnt, out);
}